// round 11
// baseline (speedup 1.0000x reference)
#include <cuda_runtime.h>
#include <cfloat>
#include <math.h>

// Problem constants
#define TT   32768          // B*S tokens
#define DD   256            // latent dim
#define DD2  512            // 2*latent dim
#define KK   4096           // n_symbols

// GEMM tiling
#define TMM  128
#define TNN  128
#define BKK  16

// Scratch
__device__ float g_bias[(size_t)KK * KK];   // 64 MB: ||c_k||^2 - 0.8*sigmoid(adj[p][k])
__device__ float g_cnorm[KK];
__device__ int   g_argmin[TT];

// ---------------------------------------------------------------------------
// 1) per-code squared norm (one warp per code)
// ---------------------------------------------------------------------------
__global__ void cnorm_kernel(const float* __restrict__ cb) {
    int warp = (blockIdx.x * blockDim.x + threadIdx.x) >> 5;
    int lane = threadIdx.x & 31;
    if (warp >= KK) return;
    const float* row = cb + (size_t)warp * DD2;
    float s = 0.f;
    #pragma unroll
    for (int i = 0; i < DD2 / 32; i++) {
        float v = row[lane + 32 * i];
        s = fmaf(v, v, s);
    }
    #pragma unroll
    for (int o = 16; o > 0; o >>= 1) s += __shfl_xor_sync(0xffffffffu, s, o);
    if (lane == 0) g_cnorm[warp] = s;
}

// ---------------------------------------------------------------------------
// 2) bias table: bias[p][k] = cnorm[k] - 0.8*sigmoid(adj[p][k])
// ---------------------------------------------------------------------------
__global__ void bias_kernel(const float* __restrict__ adj) {
    size_t i = (size_t)blockIdx.x * blockDim.x + threadIdx.x;   // float4 index
    float4 a = ((const float4*)adj)[i];
    int c0 = (int)((i & (KK / 4 - 1)) << 2);
    float4 o;
    o.x = g_cnorm[c0 + 0] - 0.8f / (1.f + __expf(-a.x));
    o.y = g_cnorm[c0 + 1] - 0.8f / (1.f + __expf(-a.y));
    o.z = g_cnorm[c0 + 2] - 0.8f / (1.f + __expf(-a.z));
    o.w = g_cnorm[c0 + 3] - 0.8f / (1.f + __expf(-a.w));
    ((float4*)g_bias)[i] = o;
}

// ---------------------------------------------------------------------------
// 3) fused distance-GEMM + running argmin.
//    d_rel(m,k) = bias[prev[m]][k] - 2*dot(z_m, c_k)   (||z||^2 row-constant)
// ---------------------------------------------------------------------------
__global__ void __launch_bounds__(256)
argmin_kernel(const float* __restrict__ zr, const float* __restrict__ zi,
              const int* __restrict__ prev, const float* __restrict__ cb) {
    __shared__ float As[BKK][TMM + 4];
    __shared__ float Bs[BKK][TNN + 4];
    __shared__ int   sprev[TMM];
    __shared__ float sval[TMM][16];
    __shared__ int   sidx[TMM][16];

    const int tid = threadIdx.x;
    const int tx = tid & 15, ty = tid >> 4;
    const int m0 = blockIdx.x * TMM;

    if (tid < TMM) {
        int p = prev[m0 + tid];
        sprev[tid] = (p >= 0 && p < KK) ? p : 0;
    }

    float best[8];
    int   bidx[8];
    #pragma unroll
    for (int i = 0; i < 8; i++) { best[i] = FLT_MAX; bidx[i] = 0; }

    for (int n0 = 0; n0 < KK; n0 += TNN) {
        float acc[8][8] = {};

        for (int kk = 0; kk < DD2; kk += BKK) {
            const float* zsrc;
            int kb;
            if (kk < DD) { zsrc = zr; kb = kk; }
            else         { zsrc = zi; kb = kk - DD; }

            float4 av[2], bv[2];
            #pragma unroll
            for (int j = 0; j < 2; j++) {
                int f = tid + 256 * j;      // float4 id 0..511
                int r = f >> 2;             // row 0..127
                int c = (f & 3) << 2;       // 0,4,8,12
                av[j] = *(const float4*)&zsrc[(size_t)(m0 + r) * DD  + kb + c];
                bv[j] = *(const float4*)&cb  [(size_t)(n0 + r) * DD2 + kk + c];
            }
            __syncthreads();
            #pragma unroll
            for (int j = 0; j < 2; j++) {
                int f = tid + 256 * j;
                int r = f >> 2;
                int c = (f & 3) << 2;
                As[c + 0][r] = av[j].x; As[c + 1][r] = av[j].y;
                As[c + 2][r] = av[j].z; As[c + 3][r] = av[j].w;
                Bs[c + 0][r] = bv[j].x; Bs[c + 1][r] = bv[j].y;
                Bs[c + 2][r] = bv[j].z; Bs[c + 3][r] = bv[j].w;
            }
            __syncthreads();

            #pragma unroll
            for (int k = 0; k < BKK; k++) {
                float a[8], b[8];
                *(float4*)&a[0] = *(const float4*)&As[k][ty * 8];
                *(float4*)&a[4] = *(const float4*)&As[k][ty * 8 + 4];
                *(float4*)&b[0] = *(const float4*)&Bs[k][tx * 8];
                *(float4*)&b[4] = *(const float4*)&Bs[k][tx * 8 + 4];
                #pragma unroll
                for (int i = 0; i < 8; i++)
                    #pragma unroll
                    for (int j = 0; j < 8; j++)
                        acc[i][j] = fmaf(a[i], b[j], acc[i][j]);
            }
        }

        // tile epilogue: bias gather + running argmin
        #pragma unroll
        for (int i = 0; i < 8; i++) {
            int m = ty * 8 + i;
            const float* brow = g_bias + (size_t)sprev[m] * KK + n0 + tx * 8;
            float bb[8];
            *(float4*)&bb[0] = *(const float4*)brow;
            *(float4*)&bb[4] = *(const float4*)(brow + 4);
            #pragma unroll
            for (int j = 0; j < 8; j++) {
                float dv = fmaf(-2.f, acc[i][j], bb[j]);
                if (dv < best[i]) { best[i] = dv; bidx[i] = n0 + tx * 8 + j; }
            }
        }
    }

    // cross-thread argmin reduce, first-min tie-break
    #pragma unroll
    for (int i = 0; i < 8; i++) {
        sval[ty * 8 + i][tx] = best[i];
        sidx[ty * 8 + i][tx] = bidx[i];
    }
    __syncthreads();
    if (tid < TMM) {
        float bv = sval[tid][0];
        int   bi = sidx[tid][0];
        #pragma unroll
        for (int j = 1; j < 16; j++) {
            float v = sval[tid][j];
            int   id = sidx[tid][j];
            if (v < bv || (v == bv && id < bi)) { bv = v; bi = id; }
        }
        g_argmin[m0 + tid] = bi;
    }
}

// ---------------------------------------------------------------------------
// 4) finalize. Output buffer = out_size FLOAT32 elements (33,816,576 bytes):
//    numpy flatten-concat with astype(float32) DROPS the imaginary part of z.
//      [ Re(z_q) : TT*DD f32 | loss : TT f32 | (float)idx : TT f32 ]
//    All writes guarded by cap_bytes.
// ---------------------------------------------------------------------------
__global__ void finalize_kernel(const float* __restrict__ zr,
                                const float* __restrict__ zi,
                                const float* __restrict__ cb,
                                float* __restrict__ out,
                                long long cap_bytes) {
    const long long ZREALF = (long long)TT * DD;       // 8,388,608
    const long long LOSS0  = ZREALF;                   // 8,388,608
    const long long IDX0   = ZREALF + TT;              // 8,421,376
    int t = blockIdx.x;
    int tid = threadIdx.x;   // 128 threads
    int idx = g_argmin[t];
    const float* c = cb + (size_t)idx * DD2;

    // loss partial over 4 dims/thread (all 512 dims)
    float s = 0.f;
    #pragma unroll
    for (int i = 0; i < 4; i++) {
        int d = tid + 128 * i;
        float cv = c[d];
        float zv = (d < DD) ? zr[(size_t)t * DD + d] : zi[(size_t)t * DD + d - DD];
        float df = cv - zv;
        s = fmaf(df, df, s);
    }

    // real-part z output: 2 floats per thread (256 dims)
    #pragma unroll
    for (int i = 0; i < 2; i++) {
        int d = tid + 128 * i;                  // 0..255
        long long fi = (long long)t * DD + d;
        if ((fi + 1) * 4 <= cap_bytes) out[fi] = c[d];
    }

    #pragma unroll
    for (int o = 16; o > 0; o >>= 1) s += __shfl_xor_sync(0xffffffffu, s, o);
    __shared__ float ws[4];
    if ((tid & 31) == 0) ws[tid >> 5] = s;
    __syncthreads();
    if (tid == 0) {
        float tot = ws[0] + ws[1] + ws[2] + ws[3];
        float loss = 1.01f * (tot * (1.f / 512.f));
        long long p;
        p = LOSS0 + t;  if ((p + 1) * 4 <= cap_bytes) out[p] = loss;
        p = IDX0 + t;   if ((p + 1) * 4 <= cap_bytes) out[p] = (float)idx;
    }
}

// ---------------------------------------------------------------------------
extern "C" void kernel_launch(void* const* d_in, const int* in_sizes, int n_in,
                              void* d_out, int out_size) {
    // Binding verified by R6 diagnostics: metadata order, element counts.
    const float* zr = nullptr;
    const float* zi = nullptr;
    const int*   prev = nullptr;
    const float* cb = nullptr;
    const float* adj = nullptr;
    for (int i = 0; i < n_in; i++) {
        long long sz = in_sizes[i];
        if (sz == 8388608)        { if (!zr) zr = (const float*)d_in[i]; else if (!zi) zi = (const float*)d_in[i]; }
        else if (sz == 32768)     { if (!prev) prev = (const int*)d_in[i]; }
        else if (sz == 2097152)   { if (!cb)   cb   = (const float*)d_in[i]; }
        else if (sz == 16777216)  { if (!adj)  adj  = (const float*)d_in[i]; }
    }
    if (!zr || !zi || !prev || !cb || !adj) return;  // "0 nodes" diagnostic

    // out_size = 8,454,144 logical elements; buffer = out_size x sizeof(f32).
    // (Minimum-size assumption: structurally crash-proof under any dtype.)
    long long cap_bytes = (long long)out_size * 4;

    cnorm_kernel<<<KK / 8, 256>>>(cb);
    bias_kernel<<<(KK * (KK / 4)) / 256, 256>>>(adj);
    argmin_kernel<<<TT / TMM, 256>>>(zr, zi, prev, cb);
    finalize_kernel<<<TT, 128>>>(zr, zi, cb, (float*)d_out, cap_bytes);
}

// round 12
// speedup vs baseline: 1.0066x; 1.0066x over previous
#include <cuda_runtime.h>
#include <cfloat>
#include <math.h>

// Problem constants
#define TT   32768          // B*S tokens
#define DD   256            // latent dim
#define DD2  512            // 2*latent dim
#define KK   4096           // n_symbols

// GEMM tiling
#define TMM  128
#define TNN  128
#define BKK  16

// Scratch
__device__ float g_bias[(size_t)KK * KK];   // 64 MB: ||c_k||^2 - 0.8*sigmoid(adj[p][k])
__device__ float g_cnorm[KK];
__device__ int   g_argmin[TT];

// ---- Blackwell packed f32x2 helpers (FFMA2 path; per-half rounding == fmaf) ----
__device__ __forceinline__ unsigned long long pk2(float lo, float hi) {
    unsigned long long r;
    asm("mov.b64 %0, {%1, %2};" : "=l"(r) : "f"(lo), "f"(hi));
    return r;
}
__device__ __forceinline__ void fma2(unsigned long long& d,
                                     unsigned long long a, unsigned long long b) {
    asm("fma.rn.f32x2 %0, %1, %2, %0;" : "+l"(d) : "l"(a), "l"(b));
}
__device__ __forceinline__ void upk2(unsigned long long v, float& lo, float& hi) {
    asm("mov.b64 {%0, %1}, %2;" : "=f"(lo), "=f"(hi) : "l"(v));
}

// ---------------------------------------------------------------------------
// 1) per-code squared norm (one warp per code)
// ---------------------------------------------------------------------------
__global__ void cnorm_kernel(const float* __restrict__ cb) {
    int warp = (blockIdx.x * blockDim.x + threadIdx.x) >> 5;
    int lane = threadIdx.x & 31;
    if (warp >= KK) return;
    const float* row = cb + (size_t)warp * DD2;
    float s = 0.f;
    #pragma unroll
    for (int i = 0; i < DD2 / 32; i++) {
        float v = row[lane + 32 * i];
        s = fmaf(v, v, s);
    }
    #pragma unroll
    for (int o = 16; o > 0; o >>= 1) s += __shfl_xor_sync(0xffffffffu, s, o);
    if (lane == 0) g_cnorm[warp] = s;
}

// ---------------------------------------------------------------------------
// 2) bias table: bias[p][k] = cnorm[k] - 0.8*sigmoid(adj[p][k])
// ---------------------------------------------------------------------------
__global__ void bias_kernel(const float* __restrict__ adj) {
    size_t i = (size_t)blockIdx.x * blockDim.x + threadIdx.x;   // float4 index
    float4 a = ((const float4*)adj)[i];
    int c0 = (int)((i & (KK / 4 - 1)) << 2);
    float4 o;
    o.x = g_cnorm[c0 + 0] - 0.8f / (1.f + __expf(-a.x));
    o.y = g_cnorm[c0 + 1] - 0.8f / (1.f + __expf(-a.y));
    o.z = g_cnorm[c0 + 2] - 0.8f / (1.f + __expf(-a.z));
    o.w = g_cnorm[c0 + 3] - 0.8f / (1.f + __expf(-a.w));
    ((float4*)g_bias)[i] = o;
}

// ---------------------------------------------------------------------------
// 3) fused distance-GEMM + running argmin, FFMA2 inner loop.
//    d_rel(m,k) = bias[prev[m]][k] - 2*dot(z_m, c_k)   (||z||^2 row-constant)
// ---------------------------------------------------------------------------
__global__ void __launch_bounds__(256)
argmin_kernel(const float* __restrict__ zr, const float* __restrict__ zi,
              const int* __restrict__ prev, const float* __restrict__ cb) {
    __shared__ float As[BKK][TMM + 4];
    __shared__ float Bs[BKK][TNN + 4];
    __shared__ int   sprev[TMM];
    __shared__ float sval[TMM][16];
    __shared__ int   sidx[TMM][16];

    const int tid = threadIdx.x;
    const int tx = tid & 15, ty = tid >> 4;
    const int m0 = blockIdx.x * TMM;

    if (tid < TMM) {
        int p = prev[m0 + tid];
        sprev[tid] = (p >= 0 && p < KK) ? p : 0;
    }

    float best[8];
    int   bidx[8];
    #pragma unroll
    for (int i = 0; i < 8; i++) { best[i] = FLT_MAX; bidx[i] = 0; }

    for (int n0 = 0; n0 < KK; n0 += TNN) {
        // packed accumulators: acc2[i][jp] = (acc[i][2jp], acc[i][2jp+1])
        unsigned long long acc2[8][4];
        #pragma unroll
        for (int i = 0; i < 8; i++)
            #pragma unroll
            for (int jp = 0; jp < 4; jp++) acc2[i][jp] = 0ull;

        for (int kk = 0; kk < DD2; kk += BKK) {
            const float* zsrc;
            int kb;
            if (kk < DD) { zsrc = zr; kb = kk; }
            else         { zsrc = zi; kb = kk - DD; }

            float4 av[2], bv[2];
            #pragma unroll
            for (int j = 0; j < 2; j++) {
                int f = tid + 256 * j;      // float4 id 0..511
                int r = f >> 2;             // row 0..127
                int c = (f & 3) << 2;       // 0,4,8,12
                av[j] = *(const float4*)&zsrc[(size_t)(m0 + r) * DD  + kb + c];
                bv[j] = *(const float4*)&cb  [(size_t)(n0 + r) * DD2 + kk + c];
            }
            __syncthreads();
            #pragma unroll
            for (int j = 0; j < 2; j++) {
                int f = tid + 256 * j;
                int r = f >> 2;
                int c = (f & 3) << 2;
                As[c + 0][r] = av[j].x; As[c + 1][r] = av[j].y;
                As[c + 2][r] = av[j].z; As[c + 3][r] = av[j].w;
                Bs[c + 0][r] = bv[j].x; Bs[c + 1][r] = bv[j].y;
                Bs[c + 2][r] = bv[j].z; Bs[c + 3][r] = bv[j].w;
            }
            __syncthreads();

            #pragma unroll
            for (int k = 0; k < BKK; k++) {
                float a[8], b[8];
                *(float4*)&a[0] = *(const float4*)&As[k][ty * 8];
                *(float4*)&a[4] = *(const float4*)&As[k][ty * 8 + 4];
                *(float4*)&b[0] = *(const float4*)&Bs[k][tx * 8];
                *(float4*)&b[4] = *(const float4*)&Bs[k][tx * 8 + 4];
                unsigned long long b2[4];
                b2[0] = pk2(b[0], b[1]);
                b2[1] = pk2(b[2], b[3]);
                b2[2] = pk2(b[4], b[5]);
                b2[3] = pk2(b[6], b[7]);
                #pragma unroll
                for (int i = 0; i < 8; i++) {
                    unsigned long long a2 = pk2(a[i], a[i]);
                    fma2(acc2[i][0], a2, b2[0]);
                    fma2(acc2[i][1], a2, b2[1]);
                    fma2(acc2[i][2], a2, b2[2]);
                    fma2(acc2[i][3], a2, b2[3]);
                }
            }
        }

        // tile epilogue: bias gather + running argmin
        #pragma unroll
        for (int i = 0; i < 8; i++) {
            int m = ty * 8 + i;
            const float* brow = g_bias + (size_t)sprev[m] * KK + n0 + tx * 8;
            float bb[8];
            *(float4*)&bb[0] = *(const float4*)brow;
            *(float4*)&bb[4] = *(const float4*)(brow + 4);
            float ac[8];
            #pragma unroll
            for (int jp = 0; jp < 4; jp++) upk2(acc2[i][jp], ac[2 * jp], ac[2 * jp + 1]);
            #pragma unroll
            for (int j = 0; j < 8; j++) {
                float dv = fmaf(-2.f, ac[j], bb[j]);
                if (dv < best[i]) { best[i] = dv; bidx[i] = n0 + tx * 8 + j; }
            }
        }
    }

    // cross-thread argmin reduce, first-min tie-break
    #pragma unroll
    for (int i = 0; i < 8; i++) {
        sval[ty * 8 + i][tx] = best[i];
        sidx[ty * 8 + i][tx] = bidx[i];
    }
    __syncthreads();
    if (tid < TMM) {
        float bv = sval[tid][0];
        int   bi = sidx[tid][0];
        #pragma unroll
        for (int j = 1; j < 16; j++) {
            float v = sval[tid][j];
            int   id = sidx[tid][j];
            if (v < bv || (v == bv && id < bi)) { bv = v; bi = id; }
        }
        g_argmin[m0 + tid] = bi;
    }
}

// ---------------------------------------------------------------------------
// 4) finalize. Output buffer = out_size FLOAT32 elements:
//      [ Re(z_q) : TT*DD f32 | loss : TT f32 | (float)idx : TT f32 ]
//    All writes guarded by cap_bytes.
// ---------------------------------------------------------------------------
__global__ void finalize_kernel(const float* __restrict__ zr,
                                const float* __restrict__ zi,
                                const float* __restrict__ cb,
                                float* __restrict__ out,
                                long long cap_bytes) {
    const long long ZREALF = (long long)TT * DD;       // 8,388,608
    const long long LOSS0  = ZREALF;                   // 8,388,608
    const long long IDX0   = ZREALF + TT;              // 8,421,376
    int t = blockIdx.x;
    int tid = threadIdx.x;   // 128 threads
    int idx = g_argmin[t];
    const float* c = cb + (size_t)idx * DD2;

    float s = 0.f;
    #pragma unroll
    for (int i = 0; i < 4; i++) {
        int d = tid + 128 * i;
        float cv = c[d];
        float zv = (d < DD) ? zr[(size_t)t * DD + d] : zi[(size_t)t * DD + d - DD];
        float df = cv - zv;
        s = fmaf(df, df, s);
    }

    #pragma unroll
    for (int i = 0; i < 2; i++) {
        int d = tid + 128 * i;                  // 0..255
        long long fi = (long long)t * DD + d;
        if ((fi + 1) * 4 <= cap_bytes) out[fi] = c[d];
    }

    #pragma unroll
    for (int o = 16; o > 0; o >>= 1) s += __shfl_xor_sync(0xffffffffu, s, o);
    __shared__ float ws[4];
    if ((tid & 31) == 0) ws[tid >> 5] = s;
    __syncthreads();
    if (tid == 0) {
        float tot = ws[0] + ws[1] + ws[2] + ws[3];
        float loss = 1.01f * (tot * (1.f / 512.f));
        long long p;
        p = LOSS0 + t;  if ((p + 1) * 4 <= cap_bytes) out[p] = loss;
        p = IDX0 + t;   if ((p + 1) * 4 <= cap_bytes) out[p] = (float)idx;
    }
}

// ---------------------------------------------------------------------------
extern "C" void kernel_launch(void* const* d_in, const int* in_sizes, int n_in,
                              void* d_out, int out_size) {
    const float* zr = nullptr;
    const float* zi = nullptr;
    const int*   prev = nullptr;
    const float* cb = nullptr;
    const float* adj = nullptr;
    for (int i = 0; i < n_in; i++) {
        long long sz = in_sizes[i];
        if (sz == 8388608)        { if (!zr) zr = (const float*)d_in[i]; else if (!zi) zi = (const float*)d_in[i]; }
        else if (sz == 32768)     { if (!prev) prev = (const int*)d_in[i]; }
        else if (sz == 2097152)   { if (!cb)   cb   = (const float*)d_in[i]; }
        else if (sz == 16777216)  { if (!adj)  adj  = (const float*)d_in[i]; }
    }
    if (!zr || !zi || !prev || !cb || !adj) return;

    long long cap_bytes = (long long)out_size * 4;   // buffer = out_size f32 elements

    cnorm_kernel<<<KK / 8, 256>>>(cb);
    bias_kernel<<<(KK * (KK / 4)) / 256, 256>>>(adj);
    argmin_kernel<<<TT / TMM, 256>>>(zr, zi, prev, cb);
    finalize_kernel<<<TT, 128>>>(zr, zi, cb, (float*)d_out, cap_bytes);
}

// round 16
// speedup vs baseline: 3.4919x; 3.4691x over previous
#include <cuda_runtime.h>
#include <cuda_fp16.h>
#include <cstdint>
#include <cfloat>
#include <math.h>

// Problem constants
#define TT   32768          // B*S tokens
#define DD   256            // latent dim
#define DD2  512            // 2*latent dim
#define KK   4096           // n_symbols
#define KST  1024           // stored halves per row: [tier0(512) | tier1(512)]

// Scratch
__device__ float  g_bias[(size_t)KK * KK];        // 64 MB
__device__ float  g_cnorm[KK];
__device__ int    g_argmin[TT];
__device__ __half g_az[(size_t)TT * KST];         // 64 MB  [z tier0 | z tier1]
__device__ __half g_bc[(size_t)KK * KST];         //  8 MB  [c tier0 | c tier1]

// ---------------- helpers ----------------
__device__ __forceinline__ uint32_t smem_u32(const void* p) {
    uint32_t a;
    asm("{ .reg .u64 t; cvta.to.shared.u64 t, %1; cvt.u32.u64 %0, t; }" : "=r"(a) : "l"(p));
    return a;
}
__device__ __forceinline__ uint32_t sw128(uint32_t off) {
    return off ^ ((off >> 3) & 0x70);
}
// fp16 2-tier split of an adjacent pair
__device__ __forceinline__ void split_pair(float e0, float e1, uint32_t& t0, uint32_t& t1) {
    __half2 h = __floats2half2_rn(e0, e1);          // x=lo=e0
    t0 = *(uint32_t*)&h;
    float r0 = e0 - __low2float(h);
    float r1 = e1 - __high2float(h);
    __half2 h1 = __floats2half2_rn(r0, r1);
    t1 = *(uint32_t*)&h1;
}
__device__ __forceinline__ void ldm_x4(uint32_t* r, uint32_t a) {
    asm volatile("ldmatrix.sync.aligned.m8n8.x4.shared.b16 {%0,%1,%2,%3}, [%4];"
                 : "=r"(r[0]), "=r"(r[1]), "=r"(r[2]), "=r"(r[3]) : "r"(a));
}
__device__ __forceinline__ void mma16816(float* c, const uint32_t* a, uint32_t b0, uint32_t b1) {
    asm("mma.sync.aligned.m16n8k16.row.col.f32.f16.f16.f32 "
        "{%0,%1,%2,%3}, {%4,%5,%6,%7}, {%8,%9}, {%0,%1,%2,%3};"
        : "+f"(c[0]), "+f"(c[1]), "+f"(c[2]), "+f"(c[3])
        : "r"(a[0]), "r"(a[1]), "r"(a[2]), "r"(a[3]), "r"(b0), "r"(b1));
}
__device__ __forceinline__ void cp16(uint32_t sdst, const void* gsrc) {
    asm volatile("cp.async.cg.shared.global [%0], [%1], 16;" :: "r"(sdst), "l"(gsrc));
}
__device__ __forceinline__ void cp_commit() {
    asm volatile("cp.async.commit_group;" ::: "memory");
}
__device__ __forceinline__ void cp_wait_all() {
    asm volatile("cp.async.wait_group 0;" ::: "memory");
}

// ---------------------------------------------------------------------------
// 0a) z tiers: g_az[m][d] d<512: tier0 of [zr|zi]; d>=512: tier1
// ---------------------------------------------------------------------------
__global__ void zsplit_kernel(const float* __restrict__ zr, const float* __restrict__ zi) {
    int i = blockIdx.x * 256 + threadIdx.x;       // 0 .. TT*DD/4-1
    int m = i >> 6;
    int d4 = (i & 63) << 2;
    float4 a = *(const float4*)(zr + (size_t)m * DD + d4);
    float4 b = *(const float4*)(zi + (size_t)m * DD + d4);
    char* base = (char*)(g_az + (size_t)m * KST);
    uint32_t p0, p1, q0, q1;
    split_pair(a.x, a.y, p0, p1);
    split_pair(a.z, a.w, q0, q1);
    *(uint2*)(base + (size_t)d4 * 2)         = make_uint2(p0, q0);
    *(uint2*)(base + (size_t)(512 + d4) * 2) = make_uint2(p1, q1);
    split_pair(b.x, b.y, p0, p1);
    split_pair(b.z, b.w, q0, q1);
    *(uint2*)(base + (size_t)(256 + d4) * 2) = make_uint2(p0, q0);
    *(uint2*)(base + (size_t)(768 + d4) * 2) = make_uint2(p1, q1);
}

// 0b) codebook tiers
__global__ void cbsplit_kernel(const float* __restrict__ cb) {
    int i = blockIdx.x * 256 + threadIdx.x;       // 0 .. KK*128-1
    int n = i >> 7;
    int d4 = (i & 127) << 2;
    float4 a = *(const float4*)(cb + (size_t)n * DD2 + d4);
    char* base = (char*)(g_bc + (size_t)n * KST);
    uint32_t p0, p1, q0, q1;
    split_pair(a.x, a.y, p0, p1);
    split_pair(a.z, a.w, q0, q1);
    *(uint2*)(base + (size_t)d4 * 2)         = make_uint2(p0, q0);
    *(uint2*)(base + (size_t)(512 + d4) * 2) = make_uint2(p1, q1);
}

// ---------------------------------------------------------------------------
// 1) per-code squared norm
// ---------------------------------------------------------------------------
__global__ void cnorm_kernel(const float* __restrict__ cb) {
    int warp = (blockIdx.x * blockDim.x + threadIdx.x) >> 5;
    int lane = threadIdx.x & 31;
    if (warp >= KK) return;
    const float* row = cb + (size_t)warp * DD2;
    float s = 0.f;
    #pragma unroll
    for (int i = 0; i < DD2 / 32; i++) {
        float v = row[lane + 32 * i];
        s = fmaf(v, v, s);
    }
    #pragma unroll
    for (int o = 16; o > 0; o >>= 1) s += __shfl_xor_sync(0xffffffffu, s, o);
    if (lane == 0) g_cnorm[warp] = s;
}

// ---------------------------------------------------------------------------
// 2) bias table: bias[p][k] = cnorm[k] - 0.8*sigmoid(adj[p][k])
// ---------------------------------------------------------------------------
__global__ void bias_kernel(const float* __restrict__ adj) {
    size_t i = (size_t)blockIdx.x * blockDim.x + threadIdx.x;
    float4 a = ((const float4*)adj)[i];
    int c0 = (int)((i & (KK / 4 - 1)) << 2);
    float4 o;
    o.x = g_cnorm[c0 + 0] - 0.8f / (1.f + __expf(-a.x));
    o.y = g_cnorm[c0 + 1] - 0.8f / (1.f + __expf(-a.y));
    o.z = g_cnorm[c0 + 2] - 0.8f / (1.f + __expf(-a.z));
    o.w = g_cnorm[c0 + 3] - 0.8f / (1.f + __expf(-a.w));
    ((float4*)g_bias)[i] = o;
}

// ---------------------------------------------------------------------------
// 3) fp16 HMMA distance-GEMM, logical K=1536 as 3 product segments:
//      seg0: z0.c0   seg1: z0.c1   seg2: z1.c0     (z1.c1 ~1e-7, omitted)
//    CTA: 128 tokens x N-sweep of 4096 codes in chunks of 128.
//    SMEM: A,B tiles 128x64 fp16 (SW128), double-buffered (64KB).
// ---------------------------------------------------------------------------
#define SM_TILE 16384
#define SM_PREV (4 * SM_TILE)
#define SMEM_MMA (SM_PREV + 512)

__global__ void __launch_bounds__(256, 2)
mma_argmin_kernel(const int* __restrict__ prev) {
    extern __shared__ char smem[];
    const uint32_t sb = smem_u32(smem);
    const int tid = threadIdx.x;
    const int lane = tid & 31, wid = tid >> 5;
    const int m0 = blockIdx.x * 128;

    int* sprev = (int*)(smem + SM_PREV);
    if (tid < 128) {
        int p = prev[m0 + tid];
        sprev[tid] = (p >= 0 && p < KK) ? p : 0;
    }
    __syncthreads();

    const int moff = (wid & 3) * 32;        // warp token offset
    const int noff = (wid >> 2) * 64;       // warp code offset within chunk
    // ldmatrix lane addressing (A and B both non-trans from K-major rows)
    const int g = lane >> 3, l8 = lane & 7;
    const int arow = ((g & 1) << 3) + l8;
    const uint32_t acol = (uint32_t)((g >> 1) << 4);
    const int brow = ((g >> 1) << 3) + l8;
    const uint32_t bcol = (uint32_t)((g & 1) << 4);

    int rows[4], prow[4];
    #pragma unroll
    for (int r = 0; r < 4; r++) {
        rows[r] = moff + (lane >> 2) + 8 * (r & 1) + 16 * (r >> 1);
        prow[r] = sprev[rows[r]];
    }
    float best[4];
    int   bidx[4];
    #pragma unroll
    for (int r = 0; r < 4; r++) { best[r] = FLT_MAX; bidx[r] = 0; }

    const __half* Ag = g_az + (size_t)m0 * KST;

    for (int n0 = 0; n0 < KK; n0 += 128) {
        float acc[2][8][4];
        #pragma unroll
        for (int mf = 0; mf < 2; mf++)
            #pragma unroll
            for (int nf = 0; nf < 8; nf++)
                #pragma unroll
                for (int e = 0; e < 4; e++) acc[mf][nf][e] = 0.f;

        const __half* Bg = g_bc + (size_t)n0 * KST;

        // preload chunk 0 (seg0: aoff=0, boff=0) into buffer 0
        #pragma unroll
        for (int j = 0; j < 4; j++) {
            int slot = tid + 256 * j;
            int row = slot >> 3, c16 = slot & 7;
            uint32_t soff = sw128((uint32_t)row * 128 + (uint32_t)c16 * 16);
            cp16(sb + 0 * SM_TILE + soff, Ag + (size_t)row * KST + c16 * 8);
            cp16(sb + 2 * SM_TILE + soff, Bg + (size_t)row * KST + c16 * 8);
        }
        cp_commit();

        for (int kk = 0; kk < 24; kk++) {       // 24 chunks of 64 halves
            const int cur = kk & 1;
            cp_wait_all();
            __syncthreads();
            if (kk < 23) {
                const int nxt = cur ^ 1;
                const int k1 = kk + 1;
                const int seg = k1 >> 3;
                const int aoff = (seg == 2) ? 512 : 0;
                const int boff = (seg == 1) ? 512 : 0;
                const int kin = (k1 & 7) * 64;
                #pragma unroll
                for (int j = 0; j < 4; j++) {
                    int slot = tid + 256 * j;
                    int row = slot >> 3, c16 = slot & 7;
                    uint32_t soff = sw128((uint32_t)row * 128 + (uint32_t)c16 * 16);
                    cp16(sb + nxt * SM_TILE + soff,
                         Ag + (size_t)row * KST + aoff + kin + c16 * 8);
                    cp16(sb + (2 + nxt) * SM_TILE + soff,
                         Bg + (size_t)row * KST + boff + kin + c16 * 8);
                }
                cp_commit();
            }
            const uint32_t sa  = sb + cur * SM_TILE;
            const uint32_t sbb = sb + (2 + cur) * SM_TILE;
            #pragma unroll
            for (int ks = 0; ks < 4; ks++) {
                uint32_t afr[2][4];
                #pragma unroll
                for (int mf = 0; mf < 2; mf++)
                    ldm_x4(afr[mf], sa + sw128((uint32_t)(moff + mf * 16 + arow) * 128
                                               + (uint32_t)ks * 32 + acol));
                #pragma unroll
                for (int nf2 = 0; nf2 < 4; nf2++) {
                    uint32_t bfr[4];
                    ldm_x4(bfr, sbb + sw128((uint32_t)(noff + nf2 * 16 + brow) * 128
                                            + (uint32_t)ks * 32 + bcol));
                    #pragma unroll
                    for (int mf = 0; mf < 2; mf++) {
                        mma16816(acc[mf][nf2 * 2 + 0], afr[mf], bfr[0], bfr[1]);
                        mma16816(acc[mf][nf2 * 2 + 1], afr[mf], bfr[2], bfr[3]);
                    }
                }
            }
        }

        // epilogue: bias gather + running argmin
        #pragma unroll
        for (int r = 0; r < 4; r++) {
            const float* bb = g_bias + (size_t)prow[r] * KK + n0 + noff + (lane & 3) * 2;
            #pragma unroll
            for (int nf = 0; nf < 8; nf++) {
                float2 bv = *(const float2*)(bb + nf * 8);
                float a0 = acc[r >> 1][nf][(r & 1) * 2 + 0];
                float a1 = acc[r >> 1][nf][(r & 1) * 2 + 1];
                float d0 = fmaf(-2.f, a0, bv.x);
                float d1 = fmaf(-2.f, a1, bv.y);
                int nidx = n0 + noff + nf * 8 + (lane & 3) * 2;
                if (d0 < best[r]) { best[r] = d0; bidx[r] = nidx; }
                if (d1 < best[r]) { best[r] = d1; bidx[r] = nidx + 1; }
            }
        }
    }

    // final cross-thread reduce: 8 owners per token row
    __syncthreads();
    float* sval = (float*)smem;                 // [128][8]
    int*   sidx = (int*)(smem + 4096);          // [128][8]
    const int col = ((wid >> 2) << 2) + (lane & 3);
    #pragma unroll
    for (int r = 0; r < 4; r++) {
        sval[rows[r] * 8 + col] = best[r];
        sidx[rows[r] * 8 + col] = bidx[r];
    }
    __syncthreads();
    if (tid < 128) {
        float bv = sval[tid * 8];
        int   bi = sidx[tid * 8];
        #pragma unroll
        for (int j = 1; j < 8; j++) {
            float v = sval[tid * 8 + j];
            int   id = sidx[tid * 8 + j];
            if (v < bv || (v == bv && id < bi)) { bv = v; bi = id; }
        }
        g_argmin[m0 + tid] = bi;
    }
}

// ---------------------------------------------------------------------------
// 4) finalize: [ Re(z_q) : TT*DD f32 | loss : TT f32 | (float)idx : TT f32 ]
// ---------------------------------------------------------------------------
__global__ void finalize_kernel(const float* __restrict__ zr,
                                const float* __restrict__ zi,
                                const float* __restrict__ cb,
                                float* __restrict__ out,
                                long long cap_bytes) {
    const long long ZREALF = (long long)TT * DD;
    const long long LOSS0  = ZREALF;
    const long long IDX0   = ZREALF + TT;
    int t = blockIdx.x;
    int tid = threadIdx.x;   // 128
    int idx = g_argmin[t];
    const float* c = cb + (size_t)idx * DD2;

    float s = 0.f;
    #pragma unroll
    for (int i = 0; i < 4; i++) {
        int d = tid + 128 * i;
        float cv = c[d];
        float zv = (d < DD) ? zr[(size_t)t * DD + d] : zi[(size_t)t * DD + d - DD];
        float df = cv - zv;
        s = fmaf(df, df, s);
    }
    #pragma unroll
    for (int i = 0; i < 2; i++) {
        int d = tid + 128 * i;
        long long fi = (long long)t * DD + d;
        if ((fi + 1) * 4 <= cap_bytes) out[fi] = c[d];
    }
    #pragma unroll
    for (int o = 16; o > 0; o >>= 1) s += __shfl_xor_sync(0xffffffffu, s, o);
    __shared__ float ws[4];
    if ((tid & 31) == 0) ws[tid >> 5] = s;
    __syncthreads();
    if (tid == 0) {
        float loss = 1.01f * ((ws[0] + ws[1] + ws[2] + ws[3]) * (1.f / 512.f));
        long long p;
        p = LOSS0 + t;  if ((p + 1) * 4 <= cap_bytes) out[p] = loss;
        p = IDX0 + t;   if ((p + 1) * 4 <= cap_bytes) out[p] = (float)idx;
    }
}

// ---------------------------------------------------------------------------
extern "C" void kernel_launch(void* const* d_in, const int* in_sizes, int n_in,
                              void* d_out, int out_size) {
    const float* zr = nullptr;
    const float* zi = nullptr;
    const int*   prev = nullptr;
    const float* cb = nullptr;
    const float* adj = nullptr;
    for (int i = 0; i < n_in; i++) {
        long long sz = in_sizes[i];
        if (sz == 8388608)        { if (!zr) zr = (const float*)d_in[i]; else if (!zi) zi = (const float*)d_in[i]; }
        else if (sz == 32768)     { if (!prev) prev = (const int*)d_in[i]; }
        else if (sz == 2097152)   { if (!cb)   cb   = (const float*)d_in[i]; }
        else if (sz == 16777216)  { if (!adj)  adj  = (const float*)d_in[i]; }
    }
    if (!zr || !zi || !prev || !cb || !adj) return;

    long long cap_bytes = (long long)out_size * 4;   // buffer = out_size f32 elements

    cudaFuncSetAttribute(mma_argmin_kernel,
                         cudaFuncAttributeMaxDynamicSharedMemorySize, SMEM_MMA);

    zsplit_kernel<<<(TT * DD / 4) / 256, 256>>>(zr, zi);
    cbsplit_kernel<<<(KK * 128) / 256, 256>>>(cb);
    cnorm_kernel<<<KK / 8, 256>>>(cb);
    bias_kernel<<<(KK * (KK / 4)) / 256, 256>>>(adj);
    mma_argmin_kernel<<<TT / 128, 256, SMEM_MMA>>>(prev);
    finalize_kernel<<<TT, 128>>>(zr, zi, cb, (float*)d_out, cap_bytes);
}